// round 8
// baseline (speedup 1.0000x reference)
#include <cuda_runtime.h>
#include <cuda_bf16.h>
#include <cstdint>
#include <cstddef>

#define BB 128
#define TT 512
#define EE 512
#define UU 1024
#define FU 4096
#define BT 65536

// ----------------------------- static scratch -------------------------------
__device__ __align__(256) int      g_tokens[BT];
__device__             int         g_tok64;
__device__ __align__(256) unsigned g_arrive[128];
__device__ __align__(256) float    g_xz[(size_t)BT * FU];  // (T,B,4U) fp32
__device__ __align__(256) float    g_hbuf[2 * BB * UU];    // ping-pong h (tf32)
__device__ __align__(256) float    g_hfinal[BB * UU];      // unrounded final h

// ------------------------------- helpers ------------------------------------
__device__ __forceinline__ float f2tf(float x) {
    unsigned u; asm("cvt.rna.tf32.f32 %0, %1;" : "=r"(u) : "f"(x));
    return __uint_as_float(u);
}
__device__ __forceinline__ void mma8(float* c, unsigned a0, unsigned a1, unsigned a2,
                                     unsigned a3, unsigned b0, unsigned b1) {
    asm("mma.sync.aligned.m16n8k8.row.col.f32.tf32.tf32.f32 "
        "{%0,%1,%2,%3}, {%4,%5,%6,%7}, {%8,%9}, {%0,%1,%2,%3};"
        : "+f"(c[0]), "+f"(c[1]), "+f"(c[2]), "+f"(c[3])
        : "r"(a0), "r"(a1), "r"(a2), "r"(a3), "r"(b0), "r"(b1));
}
__device__ __forceinline__ unsigned smem_u32(const void* p) {
    unsigned a;
    asm("{ .reg .u64 t; cvta.to.shared.u64 t, %1; cvt.u32.u64 %0, t; }" : "=r"(a) : "l"(p));
    return a;
}
__device__ __forceinline__ unsigned ld_flag(const unsigned* p) {
    unsigned v; asm volatile("ld.relaxed.gpu.global.u32 %0, [%1];" : "=r"(v) : "l"(p));
    return v;
}
__device__ __forceinline__ void st_flag(unsigned* p, unsigned v) {
    asm volatile("st.relaxed.gpu.global.u32 [%0], %1;" :: "l"(p), "r"(v));
}
__device__ __forceinline__ float2 ldcs2(const float* p) {
    float2 v; asm volatile("ld.global.cs.v2.f32 {%0,%1}, [%2];" : "=f"(v.x), "=f"(v.y) : "l"(p));
    return v;
}
// overflow-safe sigmoid: exp of a non-positive argument only
__device__ __forceinline__ float sigf(float x) {
    float e = __expf(-fabsf(x));
    float s = 1.0f / (1.0f + e);
    return x >= 0.0f ? s : 1.0f - s;
}

// -------------------------------- init --------------------------------------
__global__ void k_init() {
    int i = blockIdx.x * 256 + threadIdx.x;
    if (i < BB * UU) g_hbuf[i] = 0.0f;
    if (i < 128) g_arrive[i] = 0u;
}

// --------------------------- token probe/convert ----------------------------
// int64 sentence: every odd 32-bit word (high half) is zero (tokens < 2^31).
// int32: odd words are random tokens; OR of 16384 of them being 0 ~ impossible.
__global__ void k_probe(const unsigned* __restrict__ w) {
    __shared__ unsigned red[256];
    unsigned acc = 0;
    for (int i = threadIdx.x * 2 + 1; i < BT; i += 512) acc |= w[i];
    red[threadIdx.x] = acc;
    __syncthreads();
    for (int s = 128; s > 0; s >>= 1) {
        if (threadIdx.x < s) red[threadIdx.x] |= red[threadIdx.x + s];
        __syncthreads();
    }
    if (threadIdx.x == 0) g_tok64 = (red[0] == 0u) ? 1 : 0;
}
// single in-bounds load: compute index first (no speculative src[2*i] when int32)
__global__ void k_convert(const int* __restrict__ src) {
    int i = blockIdx.x * 256 + threadIdx.x;
    if (i < BT) {
        int idx = g_tok64 ? 2 * i : i;
        g_tokens[i] = src[idx];
    }
}

// -------------------------------- GEMM1 -------------------------------------
// xz[t][b][f] = emb[tok[b*T+t]] @ Wx + bias. CTA tile 128x128, K-chunks of 32.
__global__ void __launch_bounds__(256, 2)
k_gemm1(const float* __restrict__ emb, const float* __restrict__ Wx,
        const float* __restrict__ bias) {
    __shared__ float As[128 * 36];
    __shared__ float Bs[32 * 136];
    const int tid = threadIdx.x, lane = tid & 31, w = tid >> 5;
    const int gq = lane >> 2, tig = lane & 3;
    const int nb = blockIdx.x, mb = blockIdx.y;
    const int wM = (w >> 2) * 64, wN = (w & 3) * 32;

    float C[4][4][4];
    #pragma unroll
    for (int a = 0; a < 4; a++)
        #pragma unroll
        for (int b = 0; b < 4; b++) { C[a][b][0] = C[a][b][1] = C[a][b][2] = C[a][b][3] = 0.f; }

    #pragma unroll 1
    for (int kc = 0; kc < 16; ++kc) {
        const int k0 = kc * 32;
        __syncthreads();
        #pragma unroll
        for (int j = 0; j < 4; j++) {               // A: 128x32 gathered emb rows
            int L = tid + 256 * j, row = L >> 3, kq = L & 7;
            int tok = g_tokens[mb * 128 + row];
            float4 v = *(const float4*)(emb + (size_t)tok * EE + k0 + kq * 4);
            float* d = As + row * 36 + kq * 4;
            d[0] = f2tf(v.x); d[1] = f2tf(v.y); d[2] = f2tf(v.z); d[3] = f2tf(v.w);
        }
        #pragma unroll
        for (int j = 0; j < 4; j++) {               // B: 32x128
            int L = tid + 256 * j, k = L >> 5, nq = L & 31;
            float4 v = *(const float4*)(Wx + (size_t)(k0 + k) * FU + nb * 128 + nq * 4);
            float* d = Bs + k * 136 + nq * 4;
            d[0] = f2tf(v.x); d[1] = f2tf(v.y); d[2] = f2tf(v.z); d[3] = f2tf(v.w);
        }
        __syncthreads();
        #pragma unroll
        for (int k8 = 0; k8 < 4; k8++) {
            const int kb = k8 * 8;
            unsigned bf0[4], bf1[4];
            #pragma unroll
            for (int nf = 0; nf < 4; nf++) {
                bf0[nf] = __float_as_uint(Bs[(kb + tig) * 136 + wN + nf * 8 + gq]);
                bf1[nf] = __float_as_uint(Bs[(kb + tig + 4) * 136 + wN + nf * 8 + gq]);
            }
            #pragma unroll
            for (int mi = 0; mi < 4; mi++) {
                int r = wM + mi * 16 + gq;
                unsigned a0 = __float_as_uint(As[r * 36 + kb + tig]);
                unsigned a1 = __float_as_uint(As[(r + 8) * 36 + kb + tig]);
                unsigned a2 = __float_as_uint(As[r * 36 + kb + tig + 4]);
                unsigned a3 = __float_as_uint(As[(r + 8) * 36 + kb + tig + 4]);
                #pragma unroll
                for (int nf = 0; nf < 4; nf++) mma8(C[mi][nf], a0, a1, a2, a3, bf0[nf], bf1[nf]);
            }
        }
    }
    // epilogue: scatter into (t,b,f) order, add bias, 8B streaming stores
    #pragma unroll
    for (int mi = 0; mi < 4; mi++)
        #pragma unroll
        for (int nf = 0; nf < 4; nf++)
            #pragma unroll
            for (int half = 0; half < 2; half++) {
                int row = wM + mi * 16 + gq + half * 8;
                int m = mb * 128 + row, b = m >> 9, t = m & 511;
                int f = nb * 128 + wN + nf * 8 + tig * 2;
                float2 bv = *(const float2*)(bias + f);
                float2 o;
                o.x = C[mi][nf][half * 2 + 0] + bv.x;
                o.y = C[mi][nf][half * 2 + 1] + bv.y;
                float* p = g_xz + ((size_t)t * BB + b) * FU + f;
                asm volatile("st.global.cs.v2.f32 [%0], {%1,%2};" :: "l"(p), "f"(o.x), "f"(o.y));
            }
}

// --------------------------------- RNN ---------------------------------------
// 128 persistent CTAs x 128 threads. CTA cb owns u in [cb*8, cb*8+8), all 4 gates
// (N=32, local col = gate*8 + j). Warp tile 32(M)x32(N), K=1024 in 32-chunks.
__device__ __forceinline__ void rnn_load_chunk(const float* hsrc, int k0, float* Ab, int tid) {
    #pragma unroll
    for (int i = 0; i < 8; i++) {
        int L = tid + 128 * i, row = L >> 3, kq = L & 7;
        unsigned dst = smem_u32(Ab + row * 32 + ((kq * 4) ^ ((row & 7) << 2)));
        const float* src = hsrc + row * UU + k0 + kq * 4;
        asm volatile("cp.async.cg.shared.global [%0], [%1], 16;" :: "r"(dst), "l"(src));
    }
}

__global__ void __launch_bounds__(128, 1)
k_rnn(const float* __restrict__ Wh) {
    extern __shared__ float sm[];
    float* WHs = sm;                 // [1024][40]  tf32 Wh slice (160 KB)
    float* Ab  = sm + 1024 * 40;     // 2 x [128][32] swizzled h chunks (32 KB)
    const int tid = threadIdx.x, lane = tid & 31, w = tid >> 5;
    const int gq = lane >> 2, tig = lane & 3;
    const int cb = blockIdx.x, wM = w * 32;

    // preload Wh slice once; reused for all 512 steps
    for (int L = tid; L < 32768; L += 128) {
        int k = L >> 5, c = L & 31, g = c >> 3, j = c & 7;
        WHs[k * 40 + c] = f2tf(Wh[(size_t)k * FU + g * UU + cb * 8 + j]);
    }
    __syncthreads();

    float cst[2][2][2];
    #pragma unroll
    for (int a = 0; a < 2; a++) { cst[a][0][0] = cst[a][0][1] = cst[a][1][0] = cst[a][1][1] = 0.f; }

    #pragma unroll 1
    for (int t = 0; t < TT; t++) {
        // prefetch this step's xz slice (independent of h; issued before the
        // barrier so the ~600cyc DRAM latency hides behind wait + mma loop)
        float2 xzr[2][2][4];
        #pragma unroll
        for (int mi = 0; mi < 2; mi++)
            #pragma unroll
            for (int rh = 0; rh < 2; rh++) {
                int row = wM + mi * 16 + rh * 8 + gq;
                const float* xp = g_xz + ((size_t)t * BB + row) * FU + cb * 8 + tig * 2;
                #pragma unroll
                for (int nf = 0; nf < 4; nf++) xzr[mi][rh][nf] = ldcs2(xp + nf * UU);
            }

        if (t > 0) {
            while (ld_flag(&g_arrive[tid]) < (unsigned)t) { }
            asm volatile("fence.acq_rel.gpu;" ::: "memory");
            __syncthreads();
        }
        const float* hcur = g_hbuf + (t & 1) * (BB * UU);
        float* hnxt = g_hbuf + ((t + 1) & 1) * (BB * UU);

        float C[2][4][4];
        #pragma unroll
        for (int a = 0; a < 2; a++)
            #pragma unroll
            for (int b = 0; b < 4; b++) { C[a][b][0] = C[a][b][1] = C[a][b][2] = C[a][b][3] = 0.f; }

        rnn_load_chunk(hcur, 0, Ab, tid);
        asm volatile("cp.async.commit_group;" ::: "memory");

        // ONE barrier per k-chunk: the post-wait barrier both publishes the
        // arrived cp.async data AND orders everyone's chunk(kc-1) compute
        // before the chunk(kc+1) overwrite of that buffer.
        #pragma unroll 1
        for (int kc = 0; kc < 32; kc++) {
            asm volatile("cp.async.wait_group 0;" ::: "memory");
            __syncthreads();
            if (kc + 1 < 32) {
                rnn_load_chunk(hcur, (kc + 1) * 32, Ab + ((kc + 1) & 1) * (128 * 32), tid);
                asm volatile("cp.async.commit_group;" ::: "memory");
            }
            const float* A = Ab + (kc & 1) * (128 * 32);
            #pragma unroll
            for (int k8 = 0; k8 < 4; k8++) {
                const int kb = k8 * 8, kg = kc * 32 + kb;
                unsigned bf0[4], bf1[4];
                #pragma unroll
                for (int nf = 0; nf < 4; nf++) {
                    bf0[nf] = __float_as_uint(WHs[(kg + tig) * 40 + nf * 8 + gq]);
                    bf1[nf] = __float_as_uint(WHs[(kg + tig + 4) * 40 + nf * 8 + gq]);
                }
                #pragma unroll
                for (int mi = 0; mi < 2; mi++) {
                    int r = wM + mi * 16 + gq;
                    int sw = (gq & 7) << 2;
                    unsigned a0 = __float_as_uint(A[r * 32 + ((kb + tig) ^ sw)]);
                    unsigned a1 = __float_as_uint(A[(r + 8) * 32 + ((kb + tig) ^ sw)]);
                    unsigned a2 = __float_as_uint(A[r * 32 + ((kb + tig + 4) ^ sw)]);
                    unsigned a3 = __float_as_uint(A[(r + 8) * 32 + ((kb + tig + 4) ^ sw)]);
                    #pragma unroll
                    for (int nf = 0; nf < 4; nf++) mma8(C[mi][nf], a0, a1, a2, a3, bf0[nf], bf1[nf]);
                }
            }
        }

        // gates + state update + h publish (8B stores)
        #pragma unroll
        for (int mi = 0; mi < 2; mi++)
            #pragma unroll
            for (int rh = 0; rh < 2; rh++) {
                int row = wM + mi * 16 + rh * 8 + gq;
                float hv[2];
                #pragma unroll
                for (int jj = 0; jj < 2; jj++) {
                    int ci = rh * 2 + jj;
                    float zi = C[mi][0][ci] + (jj ? xzr[mi][rh][0].y : xzr[mi][rh][0].x);
                    float zf = C[mi][1][ci] + (jj ? xzr[mi][rh][1].y : xzr[mi][rh][1].x);
                    float zg = C[mi][2][ci] + (jj ? xzr[mi][rh][2].y : xzr[mi][rh][2].x);
                    float zo = C[mi][3][ci] + (jj ? xzr[mi][rh][3].y : xzr[mi][rh][3].x);
                    float ig = sigf(zi), fg = sigf(zf), gg = tanhf(zg), og = sigf(zo);
                    float cc = fg * cst[mi][rh][jj] + ig * gg;
                    cst[mi][rh][jj] = cc;
                    hv[jj] = og * tanhf(cc);
                }
                int u = cb * 8 + tig * 2;
                __stcg((float2*)&hnxt[row * UU + u], make_float2(f2tf(hv[0]), f2tf(hv[1])));
                if (t == TT - 1)
                    *(float2*)&g_hfinal[row * UU + u] = make_float2(hv[0], hv[1]);
            }
        __syncthreads();
        if (tid == 0) {
            asm volatile("fence.acq_rel.gpu;" ::: "memory");
            st_flag(&g_arrive[cb], (unsigned)(t + 1));
        }
    }
}

// --------------------------------- head --------------------------------------
__global__ void k_head(const float* __restrict__ W1, const float* __restrict__ b1,
                       const float* __restrict__ W2, const float* __restrict__ b2,
                       float* __restrict__ out) {
    __shared__ float hid[64];
    int b = blockIdx.x, j = threadIdx.x;
    float acc = b1[j];
    const float* hb = g_hfinal + b * UU;
    #pragma unroll 8
    for (int u = 0; u < UU; u++) acc = fmaf(hb[u], W1[u * 64 + j], acc);
    hid[j] = acc * W2[j];
    __syncthreads();
    if (j < 32) {
        float v = hid[j] + hid[j + 32];
        #pragma unroll
        for (int s = 16; s > 0; s >>= 1) v += __shfl_xor_sync(0xFFFFFFFFu, v, s);
        if (j == 0) out[b] = 1.0f / (1.0f + __expf(-(v + b2[0])));
    }
}

// -------------------------------- launch -------------------------------------
extern "C" void kernel_launch(void* const* d_in, const int* in_sizes, int n_in,
                              void* d_out, int out_size) {
    const void*  sent = d_in[0];
    const float* emb  = (const float*)d_in[1];
    const float* Wx   = (const float*)d_in[2];
    const float* Wh   = (const float*)d_in[3];
    const float* bias = (const float*)d_in[4];
    const float* W1   = (const float*)d_in[5];
    const float* b1   = (const float*)d_in[6];
    const float* W2   = (const float*)d_in[7];
    const float* b2   = (const float*)d_in[8];
    float* out = (float*)d_out;

    // idempotent, host-side, capture-safe; called unconditionally (no static guards)
    cudaFuncSetAttribute(k_rnn, cudaFuncAttributeMaxDynamicSharedMemorySize,
                         (1024 * 40 + 2 * 128 * 32) * 4);

    k_init<<<512, 256>>>();
    k_probe<<<1, 256>>>((const unsigned*)sent);
    k_convert<<<256, 256>>>((const int*)sent);
    k_gemm1<<<dim3(32, 512), 256>>>(emb, Wx, bias);
    k_rnn<<<128, 128, (1024 * 40 + 2 * 128 * 32) * 4>>>(Wh);
    k_head<<<128, 64>>>(W1, b1, W2, b2, out);
}

// round 16
// speedup vs baseline: 1.0642x; 1.0642x over previous
#include <cuda_runtime.h>
#include <cuda_bf16.h>
#include <cstdint>
#include <cstddef>

#define BB 128
#define TT 512
#define EE 512
#define UU 1024
#define FU 4096
#define BT 65536

// ----------------------------- static scratch -------------------------------
__device__ __align__(256) int      g_tokens[BT];
__device__             int         g_tok64;
__device__ __align__(256) unsigned g_arrive[128];
__device__ __align__(256) float    g_xz[(size_t)BT * FU];  // (T,B,4U) fp32
__device__ __align__(256) float    g_hbuf[2 * BB * UU];    // ping-pong h (tf32)
__device__ __align__(256) float    g_hfinal[BB * UU];      // unrounded final h

// ------------------------------- helpers ------------------------------------
__device__ __forceinline__ float f2tf(float x) {
    unsigned u; asm("cvt.rna.tf32.f32 %0, %1;" : "=r"(u) : "f"(x));
    return __uint_as_float(u);
}
__device__ __forceinline__ void mma8(float* c, unsigned a0, unsigned a1, unsigned a2,
                                     unsigned a3, unsigned b0, unsigned b1) {
    asm("mma.sync.aligned.m16n8k8.row.col.f32.tf32.tf32.f32 "
        "{%0,%1,%2,%3}, {%4,%5,%6,%7}, {%8,%9}, {%0,%1,%2,%3};"
        : "+f"(c[0]), "+f"(c[1]), "+f"(c[2]), "+f"(c[3])
        : "r"(a0), "r"(a1), "r"(a2), "r"(a3), "r"(b0), "r"(b1));
}
__device__ __forceinline__ unsigned smem_u32(const void* p) {
    unsigned a;
    asm("{ .reg .u64 t; cvta.to.shared.u64 t, %1; cvt.u32.u64 %0, t; }" : "=r"(a) : "l"(p));
    return a;
}
__device__ __forceinline__ void cpa16(unsigned dst, const void* src) {
    asm volatile("cp.async.cg.shared.global [%0], [%1], 16;" :: "r"(dst), "l"(src));
}
__device__ __forceinline__ void cpa_commit() {
    asm volatile("cp.async.commit_group;" ::: "memory");
}
__device__ __forceinline__ unsigned ld_flag(const unsigned* p) {
    unsigned v; asm volatile("ld.relaxed.gpu.global.u32 %0, [%1];" : "=r"(v) : "l"(p));
    return v;
}
__device__ __forceinline__ void st_flag(unsigned* p, unsigned v) {
    asm volatile("st.relaxed.gpu.global.u32 [%0], %1;" :: "l"(p), "r"(v));
}
__device__ __forceinline__ float2 ldcs2(const float* p) {
    float2 v; asm volatile("ld.global.cs.v2.f32 {%0,%1}, [%2];" : "=f"(v.x), "=f"(v.y) : "l"(p));
    return v;
}
__device__ __forceinline__ float sigf(float x) {
    float e = __expf(-fabsf(x));
    float s = 1.0f / (1.0f + e);
    return x >= 0.0f ? s : 1.0f - s;
}

// -------------------------------- init --------------------------------------
__global__ void k_init() {
    int i = blockIdx.x * 256 + threadIdx.x;
    if (i < BB * UU) g_hbuf[i] = 0.0f;
    if (i < 128) g_arrive[i] = 0u;
}

// --------------------------- token probe/convert ----------------------------
__global__ void k_probe(const unsigned* __restrict__ w) {
    __shared__ unsigned red[256];
    unsigned acc = 0;
    for (int i = threadIdx.x * 2 + 1; i < BT; i += 512) acc |= w[i];
    red[threadIdx.x] = acc;
    __syncthreads();
    for (int s = 128; s > 0; s >>= 1) {
        if (threadIdx.x < s) red[threadIdx.x] |= red[threadIdx.x + s];
        __syncthreads();
    }
    if (threadIdx.x == 0) g_tok64 = (red[0] == 0u) ? 1 : 0;
}
__global__ void k_convert(const int* __restrict__ src) {
    int i = blockIdx.x * 256 + threadIdx.x;
    if (i < BT) {
        int idx = g_tok64 ? 2 * i : i;
        g_tokens[i] = src[idx];
    }
}

// -------------------------------- GEMM1 -------------------------------------
// xz[t][b][f] = emb[tok[b*T+t]] @ Wx + bias. Tile 128x128, K-chunks of 32.
// 3-stage cp.async pipeline; raw fp32 operands (HW tf32 truncation).
#define G1_AS 4608            // 128*36 floats per stage
#define G1_BS 4352            // 32*136 floats per stage
#define G1_STAGE (G1_AS + G1_BS)

__global__ void __launch_bounds__(256, 2)
k_gemm1(const float* __restrict__ emb, const float* __restrict__ Wx,
        const float* __restrict__ bias) {
    extern __shared__ float g1sm[];
    const int tid = threadIdx.x, lane = tid & 31, w = tid >> 5;
    const int gq = lane >> 2, tig = lane & 3;
    const int nb = blockIdx.x, mb = blockIdx.y;
    const int wM = (w >> 2) * 64, wN = (w & 3) * 32;

    // per-thread fixed load geometry
    const int akq = tid & 7;                    // A k-quad (x4 floats)
    const int arow0 = tid >> 3;                 // A rows: arow0 + 32*j
    const float* asrc[4];
    #pragma unroll
    for (int j = 0; j < 4; j++) {
        int row = arow0 + 32 * j;
        int tok = g_tokens[mb * 128 + row];
        asrc[j] = emb + (size_t)tok * EE + akq * 4;
    }
    const int bk0 = tid >> 5, bnq = tid & 31;   // B rows: bk0 + 8*j
    // bsrc already includes bk0*FU — stage loads add only (k0 + 8*j)*FU
    const float* bsrc = Wx + (size_t)bk0 * FU + nb * 128 + bnq * 4;

    float C[4][4][4];
    #pragma unroll
    for (int a = 0; a < 4; a++)
        #pragma unroll
        for (int b = 0; b < 4; b++) { C[a][b][0] = C[a][b][1] = C[a][b][2] = C[a][b][3] = 0.f; }

    auto load_stage = [&](int kc, int st) {
        float* As = g1sm + st * G1_STAGE;
        float* Bs = As + G1_AS;
        const int k0 = kc * 32;
        #pragma unroll
        for (int j = 0; j < 4; j++) {
            int row = arow0 + 32 * j;
            cpa16(smem_u32(As + row * 36 + akq * 4), asrc[j] + k0);
        }
        #pragma unroll
        for (int j = 0; j < 4; j++) {
            int k = bk0 + 8 * j;
            cpa16(smem_u32(Bs + k * 136 + bnq * 4), bsrc + (size_t)(k0 + 8 * j) * FU);
        }
    };

    load_stage(0, 0); cpa_commit();
    load_stage(1, 1); cpa_commit();

    int st = 0;
    #pragma unroll 1
    for (int kc = 0; kc < 16; ++kc) {
        if (kc < 15) asm volatile("cp.async.wait_group 1;" ::: "memory");
        else         asm volatile("cp.async.wait_group 0;" ::: "memory");
        __syncthreads();                        // publish kc; anti-dep for kc+2
        if (kc + 2 < 16) {
            int st2 = st + 2; if (st2 >= 3) st2 -= 3;
            load_stage(kc + 2, st2); cpa_commit();
        }
        const float* As = g1sm + st * G1_STAGE;
        const float* Bs = As + G1_AS;
        #pragma unroll
        for (int k8 = 0; k8 < 4; k8++) {
            const int kb = k8 * 8;
            unsigned bf0[4], bf1[4];
            #pragma unroll
            for (int nf = 0; nf < 4; nf++) {
                bf0[nf] = __float_as_uint(Bs[(kb + tig) * 136 + wN + nf * 8 + gq]);
                bf1[nf] = __float_as_uint(Bs[(kb + tig + 4) * 136 + wN + nf * 8 + gq]);
            }
            #pragma unroll
            for (int mi = 0; mi < 4; mi++) {
                int r = wM + mi * 16 + gq;
                unsigned a0 = __float_as_uint(As[r * 36 + kb + tig]);
                unsigned a1 = __float_as_uint(As[(r + 8) * 36 + kb + tig]);
                unsigned a2 = __float_as_uint(As[r * 36 + kb + tig + 4]);
                unsigned a3 = __float_as_uint(As[(r + 8) * 36 + kb + tig + 4]);
                #pragma unroll
                for (int nf = 0; nf < 4; nf++) mma8(C[mi][nf], a0, a1, a2, a3, bf0[nf], bf1[nf]);
            }
        }
        if (++st == 3) st = 0;
    }
    // epilogue: scatter into (t,b,f) order, add bias, 8B streaming stores
    #pragma unroll
    for (int mi = 0; mi < 4; mi++)
        #pragma unroll
        for (int nf = 0; nf < 4; nf++)
            #pragma unroll
            for (int half = 0; half < 2; half++) {
                int row = wM + mi * 16 + gq + half * 8;
                int m = mb * 128 + row, b = m >> 9, t = m & 511;
                int f = nb * 128 + wN + nf * 8 + tig * 2;
                float2 bv = *(const float2*)(bias + f);
                float2 o;
                o.x = C[mi][nf][half * 2 + 0] + bv.x;
                o.y = C[mi][nf][half * 2 + 1] + bv.y;
                float* p = g_xz + ((size_t)t * BB + b) * FU + f;
                asm volatile("st.global.cs.v2.f32 [%0], {%1,%2};" :: "l"(p), "f"(o.x), "f"(o.y));
            }
}

// --------------------------------- RNN ---------------------------------------
// 128 persistent CTAs x 256 threads (8 warps, 2/SMSP). CTA cb owns u in
// [cb*8, cb*8+8), all 4 gates (N=32). Warp tile 16(M)x32(N), K=1024 in
// 32-chunks, 3-stage cp.async pipeline on h.
__device__ __forceinline__ void rnn_load_chunk(const float* hsrc, int k0, float* Ab, int tid) {
    #pragma unroll
    for (int i = 0; i < 4; i++) {
        int L = tid + 256 * i, row = L >> 3, kq = L & 7;
        unsigned dst = smem_u32(Ab + row * 32 + ((kq * 4) ^ ((row & 7) << 2)));
        cpa16(dst, hsrc + row * UU + k0 + kq * 4);
    }
}

__global__ void __launch_bounds__(256, 1)
k_rnn(const float* __restrict__ Wh) {
    extern __shared__ float sm[];
    float* WHs = sm;                 // [1024][40]  tf32 Wh slice (160 KB)
    float* Ab  = sm + 1024 * 40;     // 3 x [128][32] swizzled h chunks (48 KB)
    const int tid = threadIdx.x, lane = tid & 31, w = tid >> 5;
    const int gq = lane >> 2, tig = lane & 3;
    const int cb = blockIdx.x, wM = w * 16;

    for (int L = tid; L < 32768; L += 256) {
        int k = L >> 5, c = L & 31, g = c >> 3, j = c & 7;
        WHs[k * 40 + c] = f2tf(Wh[(size_t)k * FU + g * UU + cb * 8 + j]);
    }
    __syncthreads();

    float cst[2][2];
    cst[0][0] = cst[0][1] = cst[1][0] = cst[1][1] = 0.f;

    #pragma unroll 1
    for (int t = 0; t < TT; t++) {
        // prefetch this step's xz slice (independent of h; hides DRAM latency
        // behind the barrier wait + mma loop)
        float2 xzr[2][4];
        #pragma unroll
        for (int rh = 0; rh < 2; rh++) {
            int row = wM + rh * 8 + gq;
            const float* xp = g_xz + ((size_t)t * BB + row) * FU + cb * 8 + tig * 2;
            #pragma unroll
            for (int nf = 0; nf < 4; nf++) xzr[rh][nf] = ldcs2(xp + nf * UU);
        }

        if (t > 0) {
            if (tid < 128) {
                while (ld_flag(&g_arrive[tid]) < (unsigned)t) { }
            }
            asm volatile("fence.acq_rel.gpu;" ::: "memory");
            __syncthreads();
        }
        const float* hcur = g_hbuf + (t & 1) * (BB * UU);
        float* hnxt = g_hbuf + ((t + 1) & 1) * (BB * UU);

        float C[4][4];
        #pragma unroll
        for (int b = 0; b < 4; b++) { C[b][0] = C[b][1] = C[b][2] = C[b][3] = 0.f; }

        rnn_load_chunk(hcur, 0, Ab, tid);            cpa_commit();
        rnn_load_chunk(hcur, 32, Ab + 4096, tid);    cpa_commit();

        int st = 0;
        #pragma unroll 1
        for (int kc = 0; kc < 32; kc++) {
            if (kc < 31) asm volatile("cp.async.wait_group 1;" ::: "memory");
            else         asm volatile("cp.async.wait_group 0;" ::: "memory");
            __syncthreads();                         // publish kc; anti-dep kc+2
            if (kc + 2 < 32) {
                int st2 = st + 2; if (st2 >= 3) st2 -= 3;
                rnn_load_chunk(hcur, (kc + 2) * 32, Ab + st2 * 4096, tid);
                cpa_commit();
            }
            const float* A = Ab + st * 4096;
            #pragma unroll
            for (int k8 = 0; k8 < 4; k8++) {
                const int kb = k8 * 8, kg = kc * 32 + kb;
                unsigned bf0[4], bf1[4];
                #pragma unroll
                for (int nf = 0; nf < 4; nf++) {
                    bf0[nf] = __float_as_uint(WHs[(kg + tig) * 40 + nf * 8 + gq]);
                    bf1[nf] = __float_as_uint(WHs[(kg + tig + 4) * 40 + nf * 8 + gq]);
                }
                const int sw = gq << 2;
                unsigned a0 = __float_as_uint(A[(wM + gq) * 32 + ((kb + tig) ^ sw)]);
                unsigned a1 = __float_as_uint(A[(wM + 8 + gq) * 32 + ((kb + tig) ^ sw)]);
                unsigned a2 = __float_as_uint(A[(wM + gq) * 32 + ((kb + tig + 4) ^ sw)]);
                unsigned a3 = __float_as_uint(A[(wM + 8 + gq) * 32 + ((kb + tig + 4) ^ sw)]);
                #pragma unroll
                for (int nf = 0; nf < 4; nf++) mma8(C[nf], a0, a1, a2, a3, bf0[nf], bf1[nf]);
            }
            if (++st == 3) st = 0;
        }

        // gates + state update + h publish (8B stores)
        #pragma unroll
        for (int rh = 0; rh < 2; rh++) {
            int row = wM + rh * 8 + gq;
            float hv[2];
            #pragma unroll
            for (int jj = 0; jj < 2; jj++) {
                int ci = rh * 2 + jj;
                float zi = C[0][ci] + (jj ? xzr[rh][0].y : xzr[rh][0].x);
                float zf = C[1][ci] + (jj ? xzr[rh][1].y : xzr[rh][1].x);
                float zg = C[2][ci] + (jj ? xzr[rh][2].y : xzr[rh][2].x);
                float zo = C[3][ci] + (jj ? xzr[rh][3].y : xzr[rh][3].x);
                float ig = sigf(zi), fg = sigf(zf), gg = tanhf(zg), og = sigf(zo);
                float cc = fg * cst[rh][jj] + ig * gg;
                cst[rh][jj] = cc;
                hv[jj] = og * tanhf(cc);
            }
            int u = cb * 8 + tig * 2;
            __stcg((float2*)&hnxt[row * UU + u], make_float2(f2tf(hv[0]), f2tf(hv[1])));
            if (t == TT - 1)
                *(float2*)&g_hfinal[row * UU + u] = make_float2(hv[0], hv[1]);
        }
        __syncthreads();
        if (tid == 0) {
            asm volatile("fence.acq_rel.gpu;" ::: "memory");
            st_flag(&g_arrive[cb], (unsigned)(t + 1));
        }
    }
}

// --------------------------------- head --------------------------------------
__global__ void k_head(const float* __restrict__ W1, const float* __restrict__ b1,
                       const float* __restrict__ W2, const float* __restrict__ b2,
                       float* __restrict__ out) {
    __shared__ float hid[64];
    int b = blockIdx.x, j = threadIdx.x;
    float acc = b1[j];
    const float* hb = g_hfinal + b * UU;
    #pragma unroll 8
    for (int u = 0; u < UU; u++) acc = fmaf(hb[u], W1[u * 64 + j], acc);
    hid[j] = acc * W2[j];
    __syncthreads();
    if (j < 32) {
        float v = hid[j] + hid[j + 32];
        #pragma unroll
        for (int s = 16; s > 0; s >>= 1) v += __shfl_xor_sync(0xFFFFFFFFu, v, s);
        if (j == 0) out[b] = 1.0f / (1.0f + __expf(-(v + b2[0])));
    }
}

// -------------------------------- launch -------------------------------------
extern "C" void kernel_launch(void* const* d_in, const int* in_sizes, int n_in,
                              void* d_out, int out_size) {
    const void*  sent = d_in[0];
    const float* emb  = (const float*)d_in[1];
    const float* Wx   = (const float*)d_in[2];
    const float* Wh   = (const float*)d_in[3];
    const float* bias = (const float*)d_in[4];
    const float* W1   = (const float*)d_in[5];
    const float* b1   = (const float*)d_in[6];
    const float* W2   = (const float*)d_in[7];
    const float* b2   = (const float*)d_in[8];
    float* out = (float*)d_out;

    const int g1_smem  = 3 * G1_STAGE * 4;                 // 107520 B
    const int rnn_smem = (1024 * 40 + 3 * 128 * 32) * 4;   // 212992 B

    cudaFuncSetAttribute(k_gemm1, cudaFuncAttributeMaxDynamicSharedMemorySize, g1_smem);
    cudaFuncSetAttribute(k_rnn, cudaFuncAttributeMaxDynamicSharedMemorySize, rnn_smem);

    k_init<<<512, 256>>>();
    k_probe<<<1, 256>>>((const unsigned*)sent);
    k_convert<<<256, 256>>>((const int*)sent);
    k_gemm1<<<dim3(32, 512), 256, g1_smem>>>(emb, Wx, bias);
    k_rnn<<<128, 256, rnn_smem>>>(Wh);
    k_head<<<128, 64>>>(W1, b1, W2, b2, out);
}